// round 1
// baseline (speedup 1.0000x reference)
#include <cuda_runtime.h>

// tanhP1 bitstream stencil.
// out[t, n] = n5 * x[t-8, n], with
//   n1 = x[t]*x[t-4]
//   n2 = 1 - n1*c2[t]
//   n3 = 1 - n2*c3[t]*n1[t-1]
//   n4 = 1 - n3*c4[t]*n1[t-2]
//   n5 = 1 - n4*c5[t]*n1[t-3]
// All operands are exact {0,1} floats -> FFMA arithmetic is bit-exact.
// Pure sliding window (depth 9) over t; parallel over N columns.

#define TT 256

__global__ __launch_bounds__(128)
void tanhP1_kernel(const float4* __restrict__ x,
                   const float*  __restrict__ c2,
                   const float*  __restrict__ c3,
                   const float*  __restrict__ c4,
                   const float*  __restrict__ c5,
                   float4* __restrict__ out,
                   int n4)   // N/4 float4 columns
{
    __shared__ float4 cc[TT];
    for (int i = threadIdx.x; i < TT; i += blockDim.x)
        cc[i] = make_float4(c2[i], c3[i], c4[i], c5[i]);
    __syncthreads();

    int col = blockIdx.x * blockDim.x + threadIdx.x;
    if (col >= n4) return;

    const float4* xp = x + col;
    float4*       op = out + col;

    // Delay lines, register-resident via static circular indexing.
    // xh[j][l] holds x at time t' with t' mod 8 == j (most recent such t').
    // nh[j][l] holds n1 at time t' with t' mod 4 == j.
    float xh[8][4];
    float nh[4][4];
#pragma unroll
    for (int i = 0; i < 8; i++)
#pragma unroll
        for (int l = 0; l < 4; l++) xh[i][l] = 0.0f;
#pragma unroll
    for (int i = 0; i < 4; i++)
#pragma unroll
        for (int l = 0; l < 4; l++) nh[i][l] = 0.0f;

    for (int tb = 0; tb < TT; tb += 8) {   // tb multiple of 8 -> all mod-indices static
#pragma unroll
        for (int k = 0; k < 8; k++) {
            const int t = tb + k;
            const float4 xv = xp[(long)t * n4];
            const float4 cv = cc[t];

            // Static circular-buffer indices (tb % 8 == 0 -> depend on k only)
            const int i8  = k;            // slot of x[t-8] (and where x[t] goes)
            const int i4  = (k + 4) & 7;  // slot of x[t-4]
            const int j0  = k & 3;        // slot where n1[t] goes (== n1[t-4] slot)
            const int j1  = (k + 3) & 3;  // n1[t-1]
            const int j2  = (k + 2) & 3;  // n1[t-2]
            const int j3  = (k + 1) & 3;  // n1[t-3]

            float xt[4] = {xv.x, xv.y, xv.z, xv.w};
            float ov[4];
#pragma unroll
            for (int l = 0; l < 4; l++) {
                const float n1  = xt[l] * xh[i4][l];
                const float n2  = 1.0f - n1 * cv.x;
                const float n3  = 1.0f - n2 * (cv.y * nh[j1][l]);
                const float n4v = 1.0f - n3 * (cv.z * nh[j2][l]);
                const float n5  = 1.0f - n4v * (cv.w * nh[j3][l]);
                ov[l] = n5 * xh[i8][l];
                xh[i8][l] = xt[l];
                nh[j0][l] = n1;
            }
            op[(long)t * n4] = make_float4(ov[0], ov[1], ov[2], ov[3]);
        }
    }
}

extern "C" void kernel_launch(void* const* d_in, const int* in_sizes, int n_in,
                              void* d_out, int out_size)
{
    const float* x  = (const float*)d_in[0];
    const float* c2 = (const float*)d_in[1];
    const float* c3 = (const float*)d_in[2];
    const float* c4 = (const float*)d_in[3];
    const float* c5 = (const float*)d_in[4];

    const int T = in_sizes[1];            // 256
    const int N = in_sizes[0] / T;        // 262144
    const int n4 = N / 4;                 // float4 columns (N divisible by 4)

    const int threads = 128;
    const int blocks  = (n4 + threads - 1) / threads;
    tanhP1_kernel<<<blocks, threads>>>((const float4*)x, c2, c3, c4, c5,
                                       (float4*)d_out, n4);
}

// round 2
// speedup vs baseline: 1.2094x; 1.2094x over previous
#include <cuda_runtime.h>

// tanhP1 bitstream stencil, t-chunked for occupancy.
// out[t] = n5 * x[t-8]:
//   n1 = x[t]*x[t-4]
//   n2 = 1 - n1*c2[t]
//   n3 = 1 - n2*c3[t]*n1[t-1]
//   n4 = 1 - n3*c4[t]*n1[t-2]
//   n5 = 1 - n4*c5[t]*n1[t-3]
// Depth-9 sliding window => split T into chunks of CH with an 8-row halo
// re-read; delay-line state is rebuilt from the halo (n1 = x*x_delay4 is
// recomputable). All operands are exact {0,1} floats -> bit-exact.

#define TT 256
#define CH 64          // chunk length (multiple of 8); halo overhead 8/CH

__global__ __launch_bounds__(128)
void tanhP1_kernel(const float4* __restrict__ x,
                   const float*  __restrict__ c2,
                   const float*  __restrict__ c3,
                   const float*  __restrict__ c4,
                   const float*  __restrict__ c5,
                   float4* __restrict__ out,
                   int n4)   // N/4 float4 columns
{
    __shared__ float4 cc[TT];
    for (int i = threadIdx.x; i < TT; i += blockDim.x)
        cc[i] = make_float4(c2[i], c3[i], c4[i], c5[i]);
    __syncthreads();

    const int col = blockIdx.x * blockDim.x + threadIdx.x;
    if (col >= n4) return;
    const int t0 = blockIdx.y * CH;          // multiple of 8

    const float4* xp = x + col;
    float4*       op = out + col;

    // Delay lines. Slot of x at time s is s&7; slot of n1 at time s is s&3.
    // (t0 % 8 == 0 keeps all indices compile-time constants.)
    float xh[8][4];
    float nh[4][4];

    if (t0 == 0) {
#pragma unroll
        for (int i = 0; i < 8; i++)
#pragma unroll
            for (int l = 0; l < 4; l++) xh[i][l] = 0.0f;
#pragma unroll
        for (int i = 0; i < 4; i++)
#pragma unroll
            for (int l = 0; l < 4; l++) nh[i][l] = 0.0f;
    } else {
        // Halo: rows t0-8 .. t0-1 land in slots 0..7 (since t0 % 8 == 0).
#pragma unroll
        for (int k = 0; k < 8; k++) {
            const float4 hv = xp[(long)(t0 - 8 + k) * n4];
            xh[k][0] = hv.x; xh[k][1] = hv.y; xh[k][2] = hv.z; xh[k][3] = hv.w;
        }
        // n1[s] = x[s]*x[s-4]; need s = t0-3,t0-2,t0-1 -> slots 1,2,3.
        // x[t0-3]->slot5, x[t0-7]->slot1, etc. Slot 0 is overwritten before read.
#pragma unroll
        for (int l = 0; l < 4; l++) {
            nh[0][l] = 0.0f;
            nh[1][l] = xh[5][l] * xh[1][l];
            nh[2][l] = xh[6][l] * xh[2][l];
            nh[3][l] = xh[7][l] * xh[3][l];
        }
    }

    for (int tb = 0; tb < CH; tb += 8) {
#pragma unroll
        for (int k = 0; k < 8; k++) {
            const int t = t0 + tb + k;       // t % 8 == k
            const float4 xv = xp[(long)t * n4];
            const float4 cv = cc[t];

            const int i8 = k;                // x[t-8] slot (then receives x[t])
            const int i4 = (k + 4) & 7;      // x[t-4] slot
            const int j0 = k & 3;            // n1[t] destination
            const int j1 = (k + 3) & 3;      // n1[t-1]
            const int j2 = (k + 2) & 3;      // n1[t-2]
            const int j3 = (k + 1) & 3;      // n1[t-3]

            float xt[4] = {xv.x, xv.y, xv.z, xv.w};
            float ov[4];
#pragma unroll
            for (int l = 0; l < 4; l++) {
                const float n1  = xt[l] * xh[i4][l];
                const float n2  = 1.0f - n1  * cv.x;
                const float n3  = 1.0f - n2  * (cv.y * nh[j1][l]);
                const float n4v = 1.0f - n3  * (cv.z * nh[j2][l]);
                const float n5  = 1.0f - n4v * (cv.w * nh[j3][l]);
                ov[l] = n5 * xh[i8][l];
                xh[i8][l] = xt[l];
                nh[j0][l] = n1;
            }
            op[(long)t * n4] = make_float4(ov[0], ov[1], ov[2], ov[3]);
        }
    }
}

extern "C" void kernel_launch(void* const* d_in, const int* in_sizes, int n_in,
                              void* d_out, int out_size)
{
    const float* x  = (const float*)d_in[0];
    const float* c2 = (const float*)d_in[1];
    const float* c3 = (const float*)d_in[2];
    const float* c4 = (const float*)d_in[3];
    const float* c5 = (const float*)d_in[4];

    const int T  = in_sizes[1];           // 256
    const int N  = in_sizes[0] / T;       // 262144
    const int n4 = N / 4;

    const int threads = 128;
    dim3 grid((n4 + threads - 1) / threads, T / CH);
    tanhP1_kernel<<<grid, threads>>>((const float4*)x, c2, c3, c4, c5,
                                     (float4*)d_out, n4);
}

// round 3
// speedup vs baseline: 1.8347x; 1.5170x over previous
#include <cuda_runtime.h>

// tanhP1 bitstream stencil, t-chunked + float2 columns + explicit MLP=8.
// out[t] = n5 * x[t-8]:
//   n1 = x[t]*x[t-4]
//   n2 = 1 - n1*c2[t]
//   n3 = 1 - n2*c3[t]*n1[t-1]
//   n4 = 1 - n3*c4[t]*n1[t-2]
//   n5 = 1 - n4*c5[t]*n1[t-3]
// Depth-9 window -> chunk T into CH-row tiles with an 8-row halo re-read;
// n1 history is rebuilt from the halo (n1 = x * x_delay4). Exact {0,1}
// floats -> FFMA arithmetic is bit-exact.
//
// Round-3 changes vs round-2:
//  * float2 per thread (halves delay-line registers -> higher occupancy)
//  * all 8 loads of a t-group issued before any compute (MLP=8)

#define TT 256
#define CH 64          // chunk length (multiple of 8); halo overhead 8/CH

__global__ __launch_bounds__(256)
void tanhP1_kernel(const float2* __restrict__ x,
                   const float*  __restrict__ c2,
                   const float*  __restrict__ c3,
                   const float*  __restrict__ c4,
                   const float*  __restrict__ c5,
                   float2* __restrict__ out,
                   int n2)   // N/2 float2 columns
{
    __shared__ float4 cc[TT];
    for (int i = threadIdx.x; i < TT; i += blockDim.x)
        cc[i] = make_float4(c2[i], c3[i], c4[i], c5[i]);
    __syncthreads();

    const int col = blockIdx.x * blockDim.x + threadIdx.x;
    if (col >= n2) return;
    const int t0 = blockIdx.y * CH;          // multiple of 8

    const float2* xp = x + col;
    float2*       op = out + col;

    // Delay lines: x at time s lives in slot s&7; n1 at time s in slot s&3.
    float xh[8][2];
    float nh[4][2];

    if (t0 == 0) {
#pragma unroll
        for (int i = 0; i < 8; i++) { xh[i][0] = 0.0f; xh[i][1] = 0.0f; }
#pragma unroll
        for (int i = 0; i < 4; i++) { nh[i][0] = 0.0f; nh[i][1] = 0.0f; }
    } else {
        // Halo rows t0-8..t0-1 land in slots 0..7 (t0 % 8 == 0).
        float2 hv[8];
#pragma unroll
        for (int k = 0; k < 8; k++)
            hv[k] = xp[(long)(t0 - 8 + k) * n2];
#pragma unroll
        for (int k = 0; k < 8; k++) { xh[k][0] = hv[k].x; xh[k][1] = hv[k].y; }
        // n1[s] = x[s]*x[s-4] for s = t0-3..t0-1 -> slots 1,2,3.
#pragma unroll
        for (int l = 0; l < 2; l++) {
            nh[0][l] = 0.0f;                    // overwritten before first read
            nh[1][l] = xh[5][l] * xh[1][l];
            nh[2][l] = xh[6][l] * xh[2][l];
            nh[3][l] = xh[7][l] * xh[3][l];
        }
    }

    for (int tb = 0; tb < CH; tb += 8) {
        // ---- front-batch the 8 independent row loads (MLP = 8) ----
        float2 xv[8];
#pragma unroll
        for (int k = 0; k < 8; k++)
            xv[k] = xp[(long)(t0 + tb + k) * n2];

        // ---- compute + store the 8 rows ----
#pragma unroll
        for (int k = 0; k < 8; k++) {
            const int t = t0 + tb + k;       // t % 8 == k
            const float4 cv = cc[t];

            const int i8 = k;                // x[t-8] slot (then receives x[t])
            const int i4 = (k + 4) & 7;      // x[t-4]
            const int j0 = k & 3;            // n1[t] destination
            const int j1 = (k + 3) & 3;      // n1[t-1]
            const int j2 = (k + 2) & 3;      // n1[t-2]
            const int j3 = (k + 1) & 3;      // n1[t-3]

            float xt[2] = {xv[k].x, xv[k].y};
            float ov[2];
#pragma unroll
            for (int l = 0; l < 2; l++) {
                const float n1  = xt[l] * xh[i4][l];
                const float n2v = 1.0f - n1  * cv.x;
                const float n3  = 1.0f - n2v * (cv.y * nh[j1][l]);
                const float n4v = 1.0f - n3  * (cv.z * nh[j2][l]);
                const float n5  = 1.0f - n4v * (cv.w * nh[j3][l]);
                ov[l] = n5 * xh[i8][l];
                xh[i8][l] = xt[l];
                nh[j0][l] = n1;
            }
            op[(long)t * n2] = make_float2(ov[0], ov[1]);
        }
    }
}

extern "C" void kernel_launch(void* const* d_in, const int* in_sizes, int n_in,
                              void* d_out, int out_size)
{
    const float* x  = (const float*)d_in[0];
    const float* c2 = (const float*)d_in[1];
    const float* c3 = (const float*)d_in[2];
    const float* c4 = (const float*)d_in[3];
    const float* c5 = (const float*)d_in[4];

    const int T  = in_sizes[1];           // 256
    const int N  = in_sizes[0] / T;       // 262144
    const int n2 = N / 2;                 // float2 columns

    const int threads = 256;
    dim3 grid((n2 + threads - 1) / threads, T / CH);
    tanhP1_kernel<<<grid, threads>>>((const float2*)x, c2, c3, c4, c5,
                                     (float2*)d_out, n2);
}